// round 14
// baseline (speedup 1.0000x reference)
#include <cuda_runtime.h>
#include <cuda_bf16.h>
#include <cstdint>
#include <cstddef>

#define BB    4
#define SS    2048
#define DD    2048
#define HH    16
#define HK    2048
#define VDIM  2048
#define BS    (BB*SS)
#define NSEG  16
#define SEGLEN (SS/NSEG)

// GEMM tiling: CTA 128x128, K-chunk 32, 8 warps (2m x 4n), warp 64x32
// SMEM: XOR-swizzled rows (64B, no pad), 3-stage cp.async pipeline, 2 CTAs/SM
// Mainloop: ONE barrier per chunk (wait -> barrier -> load i+2 -> compute i)
#define TM 128
#define TN 128
#define TK 32
#define TILEB (128*64)           // 8192 B per tile (A/B, hi/lo)
#define STB   (4*TILEB)          // 32768 B per stage
#define NSTAGE 3
#define SMEM_GEMM (NSTAGE*STB)   // 98304 B -> 2 CTAs/SM (192KB < 228KB)

// ---------------- scratch (device globals; allocation forbidden) -----------
__device__ __align__(256) float g_v [(size_t)BS * HK];
__device__ __align__(256) float g_lg[(size_t)BS * HH];
__device__ __align__(256) float g_h2[(size_t)BS * DD];
__device__ __align__(256) float g_T [(size_t)BB * NSEG * HK];

__device__ __align__(256) __nv_bfloat16 g_xhi [(size_t)BS * DD];
__device__ __align__(256) __nv_bfloat16 g_xlo [(size_t)BS * DD];
__device__ __align__(256) __nv_bfloat16 g_phi [(size_t)BS * HK];
__device__ __align__(256) __nv_bfloat16 g_plo [(size_t)BS * HK];
__device__ __align__(256) __nv_bfloat16 g_ohi [(size_t)BS * VDIM];
__device__ __align__(256) __nv_bfloat16 g_olo [(size_t)BS * VDIM];
__device__ __align__(256) __nv_bfloat16 g_h1hi[(size_t)BS * DD];
__device__ __align__(256) __nv_bfloat16 g_h1lo[(size_t)BS * DD];

__device__ __align__(256) __nv_bfloat16 g_wvhi[(size_t)HK * DD];
__device__ __align__(256) __nv_bfloat16 g_wvlo[(size_t)HK * DD];
__device__ __align__(256) __nv_bfloat16 g_wohi[(size_t)VDIM * HK];
__device__ __align__(256) __nv_bfloat16 g_wolo[(size_t)VDIM * HK];
__device__ __align__(256) __nv_bfloat16 g_f1hi[(size_t)DD * (VDIM + DD)];
__device__ __align__(256) __nv_bfloat16 g_f1lo[(size_t)DD * (VDIM + DD)];
__device__ __align__(256) __nv_bfloat16 g_f2hi[(size_t)DD * DD];
__device__ __align__(256) __nv_bfloat16 g_f2lo[(size_t)DD * DD];

// ---------------- helpers ---------------------------------------------------
__device__ __forceinline__ uint32_t smem_u32(const void* p) {
    uint32_t a;
    asm("{ .reg .u64 t; cvta.to.shared.u64 t, %1; cvt.u32.u64 %0, t; }" : "=r"(a) : "l"(p));
    return a;
}
__device__ __forceinline__ void cp16(uint32_t s, const void* g) {
    asm volatile("cp.async.cg.shared.global [%0], [%1], 16;" :: "r"(s), "l"(g));
}
__device__ __forceinline__ void ldm4(uint32_t* r, uint32_t a) {
    asm volatile("ldmatrix.sync.aligned.m8n8.x4.shared.b16 {%0,%1,%2,%3}, [%4];"
        : "=r"(r[0]), "=r"(r[1]), "=r"(r[2]), "=r"(r[3]) : "r"(a));
}
__device__ __forceinline__ void mma16816(float* d, const uint32_t* a, const uint32_t* b) {
    asm volatile("mma.sync.aligned.m16n8k16.row.col.f32.bf16.bf16.f32 "
        "{%0,%1,%2,%3}, {%4,%5,%6,%7}, {%8,%9}, {%0,%1,%2,%3};"
        : "+f"(d[0]), "+f"(d[1]), "+f"(d[2]), "+f"(d[3])
        : "r"(a[0]), "r"(a[1]), "r"(a[2]), "r"(a[3]), "r"(b[0]), "r"(b[1]));
}
__device__ __forceinline__ void bf16_split(float v, __nv_bfloat16& h, __nv_bfloat16& l) {
    h = __float2bfloat16(v);
    l = __float2bfloat16(v - __bfloat162float(h));
}
// XOR swizzle: row stride 64B, 4x16B chunks, chunk ^= (row>>1)&3.
__device__ __forceinline__ uint32_t swz(int row, int ch) {
    return (uint32_t)(row * 64 + ((ch ^ ((row >> 1) & 3)) << 4));
}

// ---------------------------------------------------------------------------
// split-bf16 GEMM via mma.sync. CTA 128x128, 8 warps (warp 64x32), 256 thr,
// 3-stage pipeline, single barrier per chunk, 2 CTAs/SM.
// A:[M,K] hi/lo bf16 (split at ksplit between A0/A1), B:[N,K] hi/lo bf16.
// EPI: 0 none, 1 += vec[row/SS,col], 2 relu(+bias[col]).
// OUTBF: 0 -> Cf fp32, 1 -> Chi/Clo bf16 pair.
// ---------------------------------------------------------------------------
template<int EPI, int OUTBF>
__global__ __launch_bounds__(256, 2) void mma_gemm(
    const __nv_bfloat16* __restrict__ A0h, const __nv_bfloat16* __restrict__ A0l,
    const __nv_bfloat16* __restrict__ A1h, const __nv_bfloat16* __restrict__ A1l,
    int ksplit,
    const __nv_bfloat16* __restrict__ Bh, const __nv_bfloat16* __restrict__ Bl,
    const float* __restrict__ bias,
    float* __restrict__ Cf, __nv_bfloat16* __restrict__ Chi, __nv_bfloat16* __restrict__ Clo,
    int N, int K)
{
    extern __shared__ char smem_raw[];
    const uint32_t sb = smem_u32(smem_raw);

    const int tid  = threadIdx.x;
    const int lane = tid & 31;
    const int warp = tid >> 5;
    const int wm   = warp >> 2;        // 0..1
    const int wn   = warp & 3;         // 0..3
    const int row0 = blockIdx.y * TM;
    const int col0 = blockIdx.x * TN;
    const int lda1 = K - ksplit;
    const int nch  = K / TK;

    float acc[4][4][4];
    #pragma unroll
    for (int a = 0; a < 4; a++)
        #pragma unroll
        for (int b = 0; b < 4; b++)
            #pragma unroll
            for (int c = 0; c < 4; c++) acc[a][b][c] = 0.f;

    auto load_stage = [&](int i) {
        const uint32_t base = sb + (i % NSTAGE) * STB;
        const int kt = i * TK;
        const __nv_bfloat16 *ah, *al; int lda, koff;
        if (kt < ksplit) { ah = A0h; al = A0l; lda = ksplit; koff = kt; }
        else             { ah = A1h; al = A1l; lda = lda1;   koff = kt - ksplit; }
        #pragma unroll
        for (int it = 0; it < 2; ++it) {
            const int f = tid + it * 256;      // 0..511 = 128 rows x 4 chunks
            const int row = f >> 2, ch = f & 3;
            const uint32_t so = base + swz(row, ch);
            const size_t ga = (size_t)(row0 + row) * lda + koff + ch * 8;
            cp16(so,          ah + ga);
            cp16(so + TILEB,  al + ga);
            const size_t gb = (size_t)(col0 + row) * K + kt + ch * 8;
            cp16(so + 2 * TILEB, Bh + gb);
            cp16(so + 3 * TILEB, Bl + gb);
        }
        asm volatile("cp.async.commit_group;" ::: "memory");
    };

    load_stage(0);
    load_stage(1);
    for (int i = 0; i < nch; ++i) {
        // Ensure group i is complete. Pending at this point: {i, i+1} (or just
        // {i} on the last iteration), so wait<=1 completes group i except at
        // the end where wait<=0 is required.
        if (i + 1 < nch) {
            asm volatile("cp.async.wait_group 1;" ::: "memory");
        } else {
            asm volatile("cp.async.wait_group 0;" ::: "memory");
        }
        // Single barrier: makes stage-i fills visible to all warps AND
        // guarantees all warps finished compute(i-1) before we overwrite
        // slot (i+2)%3 == (i-1)%3 below.
        __syncthreads();
        if (i + 2 < nch) load_stage(i + 2);

        const uint32_t ab  = sb + (i % NSTAGE) * STB;
        const uint32_t alb = ab + TILEB;
        const uint32_t bb  = ab + 2 * TILEB;
        const uint32_t blb = ab + 3 * TILEB;
        #pragma unroll
        for (int ks = 0; ks < 2; ++ks) {
            uint32_t af[4][4], alf[4][4], bfr[2][4];
            const int axor = ((lane & 15) >> 1) & 3;
            const uint32_t aofs = (uint32_t)((lane & 15) * 64
                                  + (((ks * 2 + (lane >> 4)) ^ axor) << 4));
            #pragma unroll
            for (int mt = 0; mt < 4; ++mt) {
                const uint32_t r = (uint32_t)((wm * 64 + mt * 16) * 64) + aofs;
                ldm4(af[mt],  ab  + r);
                ldm4(alf[mt], alb + r);
            }
            const int bxor = ((lane & 7) >> 1) & 3;
            const uint32_t bofs = (uint32_t)(((((lane >> 4) << 3) + (lane & 7)) * 64)
                                  + (((ks * 2 + ((lane >> 3) & 1)) ^ bxor) << 4));
            #pragma unroll
            for (int np = 0; np < 2; ++np)
                ldm4(bfr[np], bb + (uint32_t)((wn * 32 + np * 16) * 64) + bofs);
            // hh + lh products (share Bh fragments)
            #pragma unroll
            for (int mt = 0; mt < 4; ++mt)
                #pragma unroll
                for (int nt = 0; nt < 4; ++nt) {
                    const uint32_t* pb = &bfr[nt >> 1][(nt & 1) * 2];
                    mma16816(acc[mt][nt], af[mt],  pb);
                    mma16816(acc[mt][nt], alf[mt], pb);
                }
            // overwrite B regs with Bl, run hl product
            #pragma unroll
            for (int np = 0; np < 2; ++np)
                ldm4(bfr[np], blb + (uint32_t)((wn * 32 + np * 16) * 64) + bofs);
            #pragma unroll
            for (int mt = 0; mt < 4; ++mt)
                #pragma unroll
                for (int nt = 0; nt < 4; ++nt)
                    mma16816(acc[mt][nt], af[mt], &bfr[nt >> 1][(nt & 1) * 2]);
        }
    }

    // ---- epilogue: direct coalesced stores --------------------------------
    const int mrow = lane >> 2;
    const int ncol = (lane & 3) * 2;
    #pragma unroll
    for (int mt = 0; mt < 4; ++mt)
        #pragma unroll
        for (int nt = 0; nt < 4; ++nt) {
            const int gc = col0 + wn * 32 + nt * 8 + ncol;
            #pragma unroll
            for (int hrow = 0; hrow < 2; ++hrow) {
                const int r = row0 + wm * 64 + mt * 16 + mrow + hrow * 8;
                float v0 = acc[mt][nt][hrow * 2];
                float v1 = acc[mt][nt][hrow * 2 + 1];
                if (EPI == 1) {
                    const float* bv = bias + (size_t)(r / SS) * N;
                    v0 += bv[gc]; v1 += bv[gc + 1];
                } else if (EPI == 2) {
                    v0 = fmaxf(v0 + bias[gc], 0.f);
                    v1 = fmaxf(v1 + bias[gc + 1], 0.f);
                }
                if (OUTBF) {
                    __nv_bfloat162 hp, lp;
                    bf16_split(v0, hp.x, lp.x);
                    bf16_split(v1, hp.y, lp.y);
                    *reinterpret_cast<__nv_bfloat162*>(Chi + (size_t)r * N + gc) = hp;
                    *reinterpret_cast<__nv_bfloat162*>(Clo + (size_t)r * N + gc) = lp;
                } else {
                    *reinterpret_cast<float2*>(Cf + (size_t)r * N + gc) = make_float2(v0, v1);
                }
            }
        }
}

// ---------------- fp32 -> bf16 hi/lo split ---------------------------------
__global__ __launch_bounds__(256) void conv_pair_kernel(
    const float* __restrict__ in, __nv_bfloat16* __restrict__ hi,
    __nv_bfloat16* __restrict__ lo, int n4)
{
    const int i = blockIdx.x * 256 + threadIdx.x;
    if (i >= n4) return;
    const float4 v = reinterpret_cast<const float4*>(in)[i];
    __nv_bfloat162 h01, h23, l01, l23;
    bf16_split(v.x, h01.x, l01.x);
    bf16_split(v.y, h01.y, l01.y);
    bf16_split(v.z, h23.x, l23.x);
    bf16_split(v.w, h23.y, l23.y);
    reinterpret_cast<__nv_bfloat162*>(hi)[2 * (size_t)i]     = h01;
    reinterpret_cast<__nv_bfloat162*>(hi)[2 * (size_t)i + 1] = h23;
    reinterpret_cast<__nv_bfloat162*>(lo)[2 * (size_t)i]     = l01;
    reinterpret_cast<__nv_bfloat162*>(lo)[2 * (size_t)i + 1] = l23;
}

// ---------------- W [K,N] fp32 -> Th/Tl [N,K] bf16 (transpose+split) -------
__global__ __launch_bounds__(256) void convT_kernel(
    const float* __restrict__ W, __nv_bfloat16* __restrict__ Th,
    __nv_bfloat16* __restrict__ Tl, int K, int N)
{
    __shared__ float t[32][33];
    const int k0 = blockIdx.y * 32, n0 = blockIdx.x * 32;
    const int tx = threadIdx.x & 31, ty = threadIdx.x >> 5;   // 32 x 8
    #pragma unroll
    for (int i = 0; i < 32; i += 8)
        t[ty + i][tx] = W[(size_t)(k0 + ty + i) * N + n0 + tx];
    __syncthreads();
    #pragma unroll
    for (int i = 0; i < 32; i += 8) {
        const float v = t[tx][ty + i];
        __nv_bfloat16 h, l;
        bf16_split(v, h, l);
        const size_t o = (size_t)(n0 + ty + i) * K + k0 + tx;
        Th[o] = h;
        Tl[o] = l;
    }
}

// ---------------- attention-gate logits ------------------------------------
__global__ __launch_bounds__(256) void att_logits_kernel(
    const float* __restrict__ x, const float* __restrict__ Watt,
    float* __restrict__ logits)
{
    __shared__ float xs[4][DD];
    __shared__ float red[4][256];
    const int r0 = blockIdx.x * 4;
    #pragma unroll
    for (int rr = 0; rr < 4; rr++)
        for (int i = threadIdx.x; i < DD; i += 256)
            xs[rr][i] = x[(size_t)(r0 + rr) * DD + i];
    __syncthreads();
    const int h = threadIdx.x & 15, ks = threadIdx.x >> 4;
    float acc[4] = {0.f, 0.f, 0.f, 0.f};
    for (int i = 0; i < DD; i += 16) {
        const float wv = Watt[(i + ks) * HH + h];
        #pragma unroll
        for (int rr = 0; rr < 4; rr++) acc[rr] += xs[rr][i + ks] * wv;
    }
    #pragma unroll
    for (int rr = 0; rr < 4; rr++) red[rr][threadIdx.x] = acc[rr];
    __syncthreads();
    if (threadIdx.x < 64) {
        const int rr = threadIdx.x >> 4, hh = threadIdx.x & 15;
        float s = 0.f;
        #pragma unroll
        for (int g = 0; g < 16; g++) s += red[rr][g * 16 + hh];
        logits[(size_t)(r0 + rr) * HH + hh] = s;
    }
}

// ---------------- coef (in-place on logits) --------------------------------
__global__ __launch_bounds__(256) void coef_kernel(
    float* __restrict__ lg, const float* __restrict__ temp)
{
    __shared__ float sb[8];
    const int b = blockIdx.x >> 4, h = blockIdx.x & 15;
    float* base = lg + (size_t)b * SS * HH + h;
    float m = -1e30f;
    for (int s = threadIdx.x; s < SS; s += 256)
        m = fmaxf(m, base[(size_t)s * HH]);
    #pragma unroll
    for (int o = 16; o; o >>= 1) m = fmaxf(m, __shfl_xor_sync(0xffffffffu, m, o));
    if ((threadIdx.x & 31) == 0) sb[threadIdx.x >> 5] = m;
    __syncthreads();
    float mm = sb[0];
    #pragma unroll
    for (int i = 1; i < 8; i++) mm = fmaxf(mm, sb[i]);
    const float T = temp[h];
    for (int s = threadIdx.x; s < SS; s += 256) {
        const float w = expf((base[(size_t)s * HH] - mm) * T);
        base[(size_t)s * HH] = w / (w * (float)(s + 1) + 1e-30f);
    }
}

// ---------------- 2-phase segmented causal scan ----------------------------
__global__ __launch_bounds__(256) void scan1_kernel(
    const float* __restrict__ v, float* __restrict__ T)
{
    const int c = blockIdx.x * 256 + threadIdx.x;
    const int seg = blockIdx.y, b = blockIdx.z;
    const float* p = v + ((size_t)b * SS + seg * SEGLEN) * HK + c;
    float a = 0.f;
    #pragma unroll 4
    for (int s = 0; s < SEGLEN; s++) a += p[(size_t)s * HK];
    T[((size_t)b * NSEG + seg) * HK + c] = a;
}

__global__ __launch_bounds__(256) void scan2_kernel(
    const float* __restrict__ v, const float* __restrict__ T,
    const float* __restrict__ coef,
    __nv_bfloat16* __restrict__ ph, __nv_bfloat16* __restrict__ pl)
{
    const int c = blockIdx.x * 256 + threadIdx.x;
    const int seg = blockIdx.y, b = blockIdx.z;
    float a = 0.f;
    for (int t = 0; t < seg; t++) a += T[((size_t)b * NSEG + t) * HK + c];
    const size_t rbase = ((size_t)b * SS + seg * SEGLEN) * HK + c;
    const float* p  = v + rbase;
    const float* cf = coef + (size_t)b * SS * HH + (size_t)seg * SEGLEN * HH + (c >> 7);
    #pragma unroll 4
    for (int s = 0; s < SEGLEN; s++) {
        a += p[(size_t)s * HK];
        const float val = cf[(size_t)s * HH] * a;
        __nv_bfloat16 h, l;
        bf16_split(val, h, l);
        ph[rbase + (size_t)s * HK] = h;
        pl[rbase + (size_t)s * HK] = l;
    }
}

// ---------------- LayerNorm ------------------------------------------------
__device__ __forceinline__ float block_sum_256(float v) {
    __shared__ float sb[8];
    #pragma unroll
    for (int o = 16; o; o >>= 1) v += __shfl_xor_sync(0xffffffffu, v, o);
    if ((threadIdx.x & 31) == 0) sb[threadIdx.x >> 5] = v;
    __syncthreads();
    float s = 0.f;
    #pragma unroll
    for (int i = 0; i < 8; i++) s += sb[i];
    __syncthreads();
    return s;
}

__global__ __launch_bounds__(256) void ln_kernel(
    const float* __restrict__ h2, const float* __restrict__ x,
    const float* __restrict__ gamma, const float* __restrict__ beta,
    float* __restrict__ out)
{
    const size_t base = (size_t)blockIdx.x * DD;
    float v[8];
    float s = 0.f;
    #pragma unroll
    for (int j = 0; j < 8; j++) {
        const int c = threadIdx.x + j * 256;
        v[j] = h2[base + c] + x[base + c];
        s += v[j];
    }
    s = block_sum_256(s);
    const float mean = s * (1.f / DD);
    float q = 0.f;
    #pragma unroll
    for (int j = 0; j < 8; j++) { v[j] -= mean; q += v[j] * v[j]; }
    q = block_sum_256(q);
    const float inv = rsqrtf(q * (1.f / DD) + 1e-6f);
    #pragma unroll
    for (int j = 0; j < 8; j++) {
        const int c = threadIdx.x + j * 256;
        out[base + c] = v[j] * inv * gamma[c] + beta[c];
    }
}

// ---------------- kernel_launch --------------------------------------------
extern "C" void kernel_launch(void* const* d_in, const int* in_sizes, int n_in,
                              void* d_out, int out_size)
{
    (void)in_sizes; (void)n_in; (void)out_size;
    const float* x      = (const float*)d_in[0];
    const float* vector = (const float*)d_in[1];
    const float* W_att  = (const float*)d_in[2];
    const float* temp   = (const float*)d_in[3];
    const float* W_val  = (const float*)d_in[4];
    const float* W_op   = (const float*)d_in[5];
    const float* ff1    = (const float*)d_in[6];
    const float* ff1_b  = (const float*)d_in[7];
    const float* ff2    = (const float*)d_in[8];
    const float* ff2_b  = (const float*)d_in[9];
    const float* gamma  = (const float*)d_in[10];
    const float* beta   = (const float*)d_in[11];
    float* out = (float*)d_out;

    float *v, *lg, *h2, *T;
    __nv_bfloat16 *xhi, *xlo, *phi, *plo, *ohi, *olo, *h1hi, *h1lo;
    __nv_bfloat16 *wvhi, *wvlo, *wohi, *wolo, *f1hi, *f1lo, *f2hi, *f2lo;
    cudaGetSymbolAddress((void**)&v,   g_v);
    cudaGetSymbolAddress((void**)&lg,  g_lg);
    cudaGetSymbolAddress((void**)&h2,  g_h2);
    cudaGetSymbolAddress((void**)&T,   g_T);
    cudaGetSymbolAddress((void**)&xhi, g_xhi);  cudaGetSymbolAddress((void**)&xlo, g_xlo);
    cudaGetSymbolAddress((void**)&phi, g_phi);  cudaGetSymbolAddress((void**)&plo, g_plo);
    cudaGetSymbolAddress((void**)&ohi, g_ohi);  cudaGetSymbolAddress((void**)&olo, g_olo);
    cudaGetSymbolAddress((void**)&h1hi, g_h1hi); cudaGetSymbolAddress((void**)&h1lo, g_h1lo);
    cudaGetSymbolAddress((void**)&wvhi, g_wvhi); cudaGetSymbolAddress((void**)&wvlo, g_wvlo);
    cudaGetSymbolAddress((void**)&wohi, g_wohi); cudaGetSymbolAddress((void**)&wolo, g_wolo);
    cudaGetSymbolAddress((void**)&f1hi, g_f1hi); cudaGetSymbolAddress((void**)&f1lo, g_f1lo);
    cudaGetSymbolAddress((void**)&f2hi, g_f2hi); cudaGetSymbolAddress((void**)&f2lo, g_f2lo);

    cudaFuncSetAttribute(mma_gemm<0,0>, cudaFuncAttributeMaxDynamicSharedMemorySize, SMEM_GEMM);
    cudaFuncSetAttribute(mma_gemm<1,1>, cudaFuncAttributeMaxDynamicSharedMemorySize, SMEM_GEMM);
    cudaFuncSetAttribute(mma_gemm<2,1>, cudaFuncAttributeMaxDynamicSharedMemorySize, SMEM_GEMM);
    cudaFuncSetAttribute(mma_gemm<2,0>, cudaFuncAttributeMaxDynamicSharedMemorySize, SMEM_GEMM);

    const dim3 tgrid(2048 / TN, BS / TM);   // (16, 64)

    // Launch order: v-GEMM is the 4th launch (index 3) -> ncu capture target.
    conv_pair_kernel<<<(BS * DD / 4 + 255) / 256, 256>>>(x, xhi, xlo, BS * DD / 4);  // 0
    convT_kernel<<<dim3(HK / 32, DD / 32), 256>>>(W_val, wvhi, wvlo, DD, HK);        // 1
    att_logits_kernel<<<BS / 4, 256>>>(x, W_att, lg);                                 // 2

    // 3: v = x @ W_values (fp32 out for the scan)  <-- profiled launch
    mma_gemm<0,0><<<tgrid, 256, SMEM_GEMM>>>(xhi, xlo, xhi, xlo, DD,
        wvhi, wvlo, nullptr, v, nullptr, nullptr, HK, DD);

    coef_kernel<<<BB * HH, 256>>>(lg, temp);                                          // 4

    // pooled = coef * cumsum(v) -> bf16 hi/lo
    scan1_kernel<<<dim3(HK / 256, NSEG, BB), 256>>>(v, T);                            // 5
    scan2_kernel<<<dim3(HK / 256, NSEG, BB), 256>>>(v, T, lg, phi, plo);              // 6

    convT_kernel<<<dim3(VDIM / 32, HK / 32), 256>>>(W_op, wohi, wolo, HK, VDIM);     // 7
    convT_kernel<<<dim3(DD / 32, (VDIM + DD) / 32), 256>>>(ff1, f1hi, f1lo, VDIM + DD, DD); // 8
    convT_kernel<<<dim3(DD / 32, DD / 32), 256>>>(ff2, f2hi, f2lo, DD, DD);           // 9

    // op = pooled @ W_op + vector -> bf16 hi/lo
    mma_gemm<1,1><<<tgrid, 256, SMEM_GEMM>>>(phi, plo, phi, plo, HK,
        wohi, wolo, vector, nullptr, ohi, olo, VDIM, HK);                             // 10

    // h1 = relu([x, op] @ ff1 + b1) -> bf16 hi/lo   (split-A, K=4096)
    mma_gemm<2,1><<<tgrid, 256, SMEM_GEMM>>>(xhi, xlo, ohi, olo, DD,
        f1hi, f1lo, ff1_b, nullptr, h1hi, h1lo, DD, VDIM + DD);                       // 11

    // h2 = relu(h1 @ ff2 + b2) -> fp32
    mma_gemm<2,0><<<tgrid, 256, SMEM_GEMM>>>(h1hi, h1lo, h1hi, h1lo, DD,
        f2hi, f2lo, ff2_b, h2, nullptr, nullptr, DD, DD);                             // 12

    // out = LayerNorm(h2 + x)
    ln_kernel<<<BS, 256>>>(h2, x, gamma, beta, out);                                  // 13
}

// round 15
// speedup vs baseline: 1.0085x; 1.0085x over previous
#include <cuda_runtime.h>
#include <cuda_bf16.h>
#include <cstdint>
#include <cstddef>

#define BB    4
#define SS    2048
#define DD    2048
#define HH    16
#define HK    2048
#define VDIM  2048
#define BS    (BB*SS)
#define NSEG  16
#define SEGLEN (SS/NSEG)

// GEMM tiling: CTA 128x128, K-chunk 32, 8 warps (2m x 4n), warp 64x32
// SMEM: XOR-swizzled rows (64B, no pad), 3-stage cp.async pipeline, 2 CTAs/SM
// Inner loop: three full product passes (hh, lh, hl) -> no adjacent
// accumulator RAW on the tensor pipe.
#define TM 128
#define TN 128
#define TK 32
#define TILEB (128*64)           // 8192 B per tile (A/B, hi/lo)
#define STB   (4*TILEB)          // 32768 B per stage
#define NSTAGE 3
#define SMEM_GEMM (NSTAGE*STB)   // 98304 B -> 2 CTAs/SM (192KB < 228KB)

// ---------------- scratch (device globals; allocation forbidden) -----------
__device__ __align__(256) float g_v [(size_t)BS * HK];
__device__ __align__(256) float g_lg[(size_t)BS * HH];
__device__ __align__(256) float g_h2[(size_t)BS * DD];
__device__ __align__(256) float g_T [(size_t)BB * NSEG * HK];

__device__ __align__(256) __nv_bfloat16 g_xhi [(size_t)BS * DD];
__device__ __align__(256) __nv_bfloat16 g_xlo [(size_t)BS * DD];
__device__ __align__(256) __nv_bfloat16 g_phi [(size_t)BS * HK];
__device__ __align__(256) __nv_bfloat16 g_plo [(size_t)BS * HK];
__device__ __align__(256) __nv_bfloat16 g_ohi [(size_t)BS * VDIM];
__device__ __align__(256) __nv_bfloat16 g_olo [(size_t)BS * VDIM];
__device__ __align__(256) __nv_bfloat16 g_h1hi[(size_t)BS * DD];
__device__ __align__(256) __nv_bfloat16 g_h1lo[(size_t)BS * DD];

__device__ __align__(256) __nv_bfloat16 g_wvhi[(size_t)HK * DD];
__device__ __align__(256) __nv_bfloat16 g_wvlo[(size_t)HK * DD];
__device__ __align__(256) __nv_bfloat16 g_wohi[(size_t)VDIM * HK];
__device__ __align__(256) __nv_bfloat16 g_wolo[(size_t)VDIM * HK];
__device__ __align__(256) __nv_bfloat16 g_f1hi[(size_t)DD * (VDIM + DD)];
__device__ __align__(256) __nv_bfloat16 g_f1lo[(size_t)DD * (VDIM + DD)];
__device__ __align__(256) __nv_bfloat16 g_f2hi[(size_t)DD * DD];
__device__ __align__(256) __nv_bfloat16 g_f2lo[(size_t)DD * DD];

// ---------------- helpers ---------------------------------------------------
__device__ __forceinline__ uint32_t smem_u32(const void* p) {
    uint32_t a;
    asm("{ .reg .u64 t; cvta.to.shared.u64 t, %1; cvt.u32.u64 %0, t; }" : "=r"(a) : "l"(p));
    return a;
}
__device__ __forceinline__ void cp16(uint32_t s, const void* g) {
    asm volatile("cp.async.cg.shared.global [%0], [%1], 16;" :: "r"(s), "l"(g));
}
__device__ __forceinline__ void ldm4(uint32_t* r, uint32_t a) {
    asm volatile("ldmatrix.sync.aligned.m8n8.x4.shared.b16 {%0,%1,%2,%3}, [%4];"
        : "=r"(r[0]), "=r"(r[1]), "=r"(r[2]), "=r"(r[3]) : "r"(a));
}
__device__ __forceinline__ void mma16816(float* d, const uint32_t* a, const uint32_t* b) {
    asm volatile("mma.sync.aligned.m16n8k16.row.col.f32.bf16.bf16.f32 "
        "{%0,%1,%2,%3}, {%4,%5,%6,%7}, {%8,%9}, {%0,%1,%2,%3};"
        : "+f"(d[0]), "+f"(d[1]), "+f"(d[2]), "+f"(d[3])
        : "r"(a[0]), "r"(a[1]), "r"(a[2]), "r"(a[3]), "r"(b[0]), "r"(b[1]));
}
__device__ __forceinline__ void bf16_split(float v, __nv_bfloat16& h, __nv_bfloat16& l) {
    h = __float2bfloat16(v);
    l = __float2bfloat16(v - __bfloat162float(h));
}
// XOR swizzle: row stride 64B, 4x16B chunks, chunk ^= (row>>1)&3.
__device__ __forceinline__ uint32_t swz(int row, int ch) {
    return (uint32_t)(row * 64 + ((ch ^ ((row >> 1) & 3)) << 4));
}

// ---------------------------------------------------------------------------
// split-bf16 GEMM via mma.sync. CTA 128x128, 8 warps (warp 64x32), 256 thr,
// 3-stage pipeline, 2 CTAs/SM. A:[M,K] hi/lo bf16 (split at ksplit between
// A0/A1), B:[N,K] hi/lo bf16 (pre-transposed).
// EPI: 0 none, 1 += vec[row/SS,col], 2 relu(+bias[col]).
// OUTBF: 0 -> Cf fp32, 1 -> Chi/Clo bf16 pair.
// ---------------------------------------------------------------------------
template<int EPI, int OUTBF>
__global__ __launch_bounds__(256, 2) void mma_gemm(
    const __nv_bfloat16* __restrict__ A0h, const __nv_bfloat16* __restrict__ A0l,
    const __nv_bfloat16* __restrict__ A1h, const __nv_bfloat16* __restrict__ A1l,
    int ksplit,
    const __nv_bfloat16* __restrict__ Bh, const __nv_bfloat16* __restrict__ Bl,
    const float* __restrict__ bias,
    float* __restrict__ Cf, __nv_bfloat16* __restrict__ Chi, __nv_bfloat16* __restrict__ Clo,
    int N, int K)
{
    extern __shared__ char smem_raw[];
    const uint32_t sb = smem_u32(smem_raw);

    const int tid  = threadIdx.x;
    const int lane = tid & 31;
    const int warp = tid >> 5;
    const int wm   = warp >> 2;        // 0..1
    const int wn   = warp & 3;         // 0..3
    const int row0 = blockIdx.y * TM;
    const int col0 = blockIdx.x * TN;
    const int lda1 = K - ksplit;
    const int nch  = K / TK;

    float acc[4][4][4];
    #pragma unroll
    for (int a = 0; a < 4; a++)
        #pragma unroll
        for (int b = 0; b < 4; b++)
            #pragma unroll
            for (int c = 0; c < 4; c++) acc[a][b][c] = 0.f;

    auto load_stage = [&](int i) {
        const uint32_t base = sb + (i % NSTAGE) * STB;
        const int kt = i * TK;
        const __nv_bfloat16 *ah, *al; int lda, koff;
        if (kt < ksplit) { ah = A0h; al = A0l; lda = ksplit; koff = kt; }
        else             { ah = A1h; al = A1l; lda = lda1;   koff = kt - ksplit; }
        #pragma unroll
        for (int it = 0; it < 2; ++it) {
            const int f = tid + it * 256;      // 0..511 = 128 rows x 4 chunks
            const int row = f >> 2, ch = f & 3;
            const uint32_t so = base + swz(row, ch);
            const size_t ga = (size_t)(row0 + row) * lda + koff + ch * 8;
            cp16(so,          ah + ga);
            cp16(so + TILEB,  al + ga);
            const size_t gb = (size_t)(col0 + row) * K + kt + ch * 8;
            cp16(so + 2 * TILEB, Bh + gb);
            cp16(so + 3 * TILEB, Bl + gb);
        }
        asm volatile("cp.async.commit_group;" ::: "memory");
    };

    load_stage(0);
    load_stage(1);
    for (int i = 0; i < nch; ++i) {
        if (i + 2 < nch) {
            load_stage(i + 2);
            asm volatile("cp.async.wait_group 2;" ::: "memory");
        } else if (i + 1 < nch) {
            asm volatile("cp.async.wait_group 1;" ::: "memory");
        } else {
            asm volatile("cp.async.wait_group 0;" ::: "memory");
        }
        __syncthreads();

        const uint32_t ab  = sb + (i % NSTAGE) * STB;
        const uint32_t alb = ab + TILEB;
        const uint32_t bb  = ab + 2 * TILEB;
        const uint32_t blb = ab + 3 * TILEB;
        #pragma unroll
        for (int ks = 0; ks < 2; ++ks) {
            uint32_t af[4][4], alf[4][4], bfr[2][4];
            const int axor = ((lane & 15) >> 1) & 3;
            const uint32_t aofs = (uint32_t)((lane & 15) * 64
                                  + (((ks * 2 + (lane >> 4)) ^ axor) << 4));
            #pragma unroll
            for (int mt = 0; mt < 4; ++mt) {
                const uint32_t r = (uint32_t)((wm * 64 + mt * 16) * 64) + aofs;
                ldm4(af[mt],  ab  + r);
                ldm4(alf[mt], alb + r);
            }
            const int bxor = ((lane & 7) >> 1) & 3;
            const uint32_t bofs = (uint32_t)(((((lane >> 4) << 3) + (lane & 7)) * 64)
                                  + (((ks * 2 + ((lane >> 3) & 1)) ^ bxor) << 4));
            #pragma unroll
            for (int np = 0; np < 2; ++np)
                ldm4(bfr[np], bb + (uint32_t)((wn * 32 + np * 16) * 64) + bofs);
            // Pass 1: all hh products (16 independent accumulators)
            #pragma unroll
            for (int mt = 0; mt < 4; ++mt)
                #pragma unroll
                for (int nt = 0; nt < 4; ++nt)
                    mma16816(acc[mt][nt], af[mt], &bfr[nt >> 1][(nt & 1) * 2]);
            // Pass 2: all lh products (15 independent mma between same-acc touches)
            #pragma unroll
            for (int mt = 0; mt < 4; ++mt)
                #pragma unroll
                for (int nt = 0; nt < 4; ++nt)
                    mma16816(acc[mt][nt], alf[mt], &bfr[nt >> 1][(nt & 1) * 2]);
            // Reload B regs with Bl, pass 3: all hl products
            #pragma unroll
            for (int np = 0; np < 2; ++np)
                ldm4(bfr[np], blb + (uint32_t)((wn * 32 + np * 16) * 64) + bofs);
            #pragma unroll
            for (int mt = 0; mt < 4; ++mt)
                #pragma unroll
                for (int nt = 0; nt < 4; ++nt)
                    mma16816(acc[mt][nt], af[mt], &bfr[nt >> 1][(nt & 1) * 2]);
        }
        __syncthreads();
    }

    // ---- epilogue: direct coalesced stores --------------------------------
    const int mrow = lane >> 2;
    const int ncol = (lane & 3) * 2;
    #pragma unroll
    for (int mt = 0; mt < 4; ++mt)
        #pragma unroll
        for (int nt = 0; nt < 4; ++nt) {
            const int gc = col0 + wn * 32 + nt * 8 + ncol;
            #pragma unroll
            for (int hrow = 0; hrow < 2; ++hrow) {
                const int r = row0 + wm * 64 + mt * 16 + mrow + hrow * 8;
                float v0 = acc[mt][nt][hrow * 2];
                float v1 = acc[mt][nt][hrow * 2 + 1];
                if (EPI == 1) {
                    const float* bv = bias + (size_t)(r / SS) * N;
                    v0 += bv[gc]; v1 += bv[gc + 1];
                } else if (EPI == 2) {
                    v0 = fmaxf(v0 + bias[gc], 0.f);
                    v1 = fmaxf(v1 + bias[gc + 1], 0.f);
                }
                if (OUTBF) {
                    __nv_bfloat162 hp, lp;
                    bf16_split(v0, hp.x, lp.x);
                    bf16_split(v1, hp.y, lp.y);
                    *reinterpret_cast<__nv_bfloat162*>(Chi + (size_t)r * N + gc) = hp;
                    *reinterpret_cast<__nv_bfloat162*>(Clo + (size_t)r * N + gc) = lp;
                } else {
                    *reinterpret_cast<float2*>(Cf + (size_t)r * N + gc) = make_float2(v0, v1);
                }
            }
        }
}

// ---------------- fp32 -> bf16 hi/lo split ---------------------------------
__global__ __launch_bounds__(256) void conv_pair_kernel(
    const float* __restrict__ in, __nv_bfloat16* __restrict__ hi,
    __nv_bfloat16* __restrict__ lo, int n4)
{
    const int i = blockIdx.x * 256 + threadIdx.x;
    if (i >= n4) return;
    const float4 v = reinterpret_cast<const float4*>(in)[i];
    __nv_bfloat162 h01, h23, l01, l23;
    bf16_split(v.x, h01.x, l01.x);
    bf16_split(v.y, h01.y, l01.y);
    bf16_split(v.z, h23.x, l23.x);
    bf16_split(v.w, h23.y, l23.y);
    reinterpret_cast<__nv_bfloat162*>(hi)[2 * (size_t)i]     = h01;
    reinterpret_cast<__nv_bfloat162*>(hi)[2 * (size_t)i + 1] = h23;
    reinterpret_cast<__nv_bfloat162*>(lo)[2 * (size_t)i]     = l01;
    reinterpret_cast<__nv_bfloat162*>(lo)[2 * (size_t)i + 1] = l23;
}

// ---------------- W [K,N] fp32 -> Th/Tl [N,K] bf16 (transpose+split) -------
__global__ __launch_bounds__(256) void convT_kernel(
    const float* __restrict__ W, __nv_bfloat16* __restrict__ Th,
    __nv_bfloat16* __restrict__ Tl, int K, int N)
{
    __shared__ float t[32][33];
    const int k0 = blockIdx.y * 32, n0 = blockIdx.x * 32;
    const int tx = threadIdx.x & 31, ty = threadIdx.x >> 5;   // 32 x 8
    #pragma unroll
    for (int i = 0; i < 32; i += 8)
        t[ty + i][tx] = W[(size_t)(k0 + ty + i) * N + n0 + tx];
    __syncthreads();
    #pragma unroll
    for (int i = 0; i < 32; i += 8) {
        const float v = t[tx][ty + i];
        __nv_bfloat16 h, l;
        bf16_split(v, h, l);
        const size_t o = (size_t)(n0 + ty + i) * K + k0 + tx;
        Th[o] = h;
        Tl[o] = l;
    }
}

// ---------------- attention-gate logits ------------------------------------
__global__ __launch_bounds__(256) void att_logits_kernel(
    const float* __restrict__ x, const float* __restrict__ Watt,
    float* __restrict__ logits)
{
    __shared__ float xs[4][DD];
    __shared__ float red[4][256];
    const int r0 = blockIdx.x * 4;
    #pragma unroll
    for (int rr = 0; rr < 4; rr++)
        for (int i = threadIdx.x; i < DD; i += 256)
            xs[rr][i] = x[(size_t)(r0 + rr) * DD + i];
    __syncthreads();
    const int h = threadIdx.x & 15, ks = threadIdx.x >> 4;
    float acc[4] = {0.f, 0.f, 0.f, 0.f};
    for (int i = 0; i < DD; i += 16) {
        const float wv = Watt[(i + ks) * HH + h];
        #pragma unroll
        for (int rr = 0; rr < 4; rr++) acc[rr] += xs[rr][i + ks] * wv;
    }
    #pragma unroll
    for (int rr = 0; rr < 4; rr++) red[rr][threadIdx.x] = acc[rr];
    __syncthreads();
    if (threadIdx.x < 64) {
        const int rr = threadIdx.x >> 4, hh = threadIdx.x & 15;
        float s = 0.f;
        #pragma unroll
        for (int g = 0; g < 16; g++) s += red[rr][g * 16 + hh];
        logits[(size_t)(r0 + rr) * HH + hh] = s;
    }
}

// ---------------- coef (in-place on logits) --------------------------------
__global__ __launch_bounds__(256) void coef_kernel(
    float* __restrict__ lg, const float* __restrict__ temp)
{
    __shared__ float sb[8];
    const int b = blockIdx.x >> 4, h = blockIdx.x & 15;
    float* base = lg + (size_t)b * SS * HH + h;
    float m = -1e30f;
    for (int s = threadIdx.x; s < SS; s += 256)
        m = fmaxf(m, base[(size_t)s * HH]);
    #pragma unroll
    for (int o = 16; o; o >>= 1) m = fmaxf(m, __shfl_xor_sync(0xffffffffu, m, o));
    if ((threadIdx.x & 31) == 0) sb[threadIdx.x >> 5] = m;
    __syncthreads();
    float mm = sb[0];
    #pragma unroll
    for (int i = 1; i < 8; i++) mm = fmaxf(mm, sb[i]);
    const float T = temp[h];
    for (int s = threadIdx.x; s < SS; s += 256) {
        const float w = expf((base[(size_t)s * HH] - mm) * T);
        base[(size_t)s * HH] = w / (w * (float)(s + 1) + 1e-30f);
    }
}

// ---------------- 2-phase segmented causal scan ----------------------------
__global__ __launch_bounds__(256) void scan1_kernel(
    const float* __restrict__ v, float* __restrict__ T)
{
    const int c = blockIdx.x * 256 + threadIdx.x;
    const int seg = blockIdx.y, b = blockIdx.z;
    const float* p = v + ((size_t)b * SS + seg * SEGLEN) * HK + c;
    float a = 0.f;
    #pragma unroll 4
    for (int s = 0; s < SEGLEN; s++) a += p[(size_t)s * HK];
    T[((size_t)b * NSEG + seg) * HK + c] = a;
}

__global__ __launch_bounds__(256) void scan2_kernel(
    const float* __restrict__ v, const float* __restrict__ T,
    const float* __restrict__ coef,
    __nv_bfloat16* __restrict__ ph, __nv_bfloat16* __restrict__ pl)
{
    const int c = blockIdx.x * 256 + threadIdx.x;
    const int seg = blockIdx.y, b = blockIdx.z;
    float a = 0.f;
    for (int t = 0; t < seg; t++) a += T[((size_t)b * NSEG + t) * HK + c];
    const size_t rbase = ((size_t)b * SS + seg * SEGLEN) * HK + c;
    const float* p  = v + rbase;
    const float* cf = coef + (size_t)b * SS * HH + (size_t)seg * SEGLEN * HH + (c >> 7);
    #pragma unroll 4
    for (int s = 0; s < SEGLEN; s++) {
        a += p[(size_t)s * HK];
        const float val = cf[(size_t)s * HH] * a;
        __nv_bfloat16 h, l;
        bf16_split(val, h, l);
        ph[rbase + (size_t)s * HK] = h;
        pl[rbase + (size_t)s * HK] = l;
    }
}

// ---------------- LayerNorm ------------------------------------------------
__device__ __forceinline__ float block_sum_256(float v) {
    __shared__ float sb[8];
    #pragma unroll
    for (int o = 16; o; o >>= 1) v += __shfl_xor_sync(0xffffffffu, v, o);
    if ((threadIdx.x & 31) == 0) sb[threadIdx.x >> 5] = v;
    __syncthreads();
    float s = 0.f;
    #pragma unroll
    for (int i = 0; i < 8; i++) s += sb[i];
    __syncthreads();
    return s;
}

__global__ __launch_bounds__(256) void ln_kernel(
    const float* __restrict__ h2, const float* __restrict__ x,
    const float* __restrict__ gamma, const float* __restrict__ beta,
    float* __restrict__ out)
{
    const size_t base = (size_t)blockIdx.x * DD;
    float v[8];
    float s = 0.f;
    #pragma unroll
    for (int j = 0; j < 8; j++) {
        const int c = threadIdx.x + j * 256;
        v[j] = h2[base + c] + x[base + c];
        s += v[j];
    }
    s = block_sum_256(s);
    const float mean = s * (1.f / DD);
    float q = 0.f;
    #pragma unroll
    for (int j = 0; j < 8; j++) { v[j] -= mean; q += v[j] * v[j]; }
    q = block_sum_256(q);
    const float inv = rsqrtf(q * (1.f / DD) + 1e-6f);
    #pragma unroll
    for (int j = 0; j < 8; j++) {
        const int c = threadIdx.x + j * 256;
        out[base + c] = v[j] * inv * gamma[c] + beta[c];
    }
}

// ---------------- kernel_launch --------------------------------------------
extern "C" void kernel_launch(void* const* d_in, const int* in_sizes, int n_in,
                              void* d_out, int out_size)
{
    (void)in_sizes; (void)n_in; (void)out_size;
    const float* x      = (const float*)d_in[0];
    const float* vector = (const float*)d_in[1];
    const float* W_att  = (const float*)d_in[2];
    const float* temp   = (const float*)d_in[3];
    const float* W_val  = (const float*)d_in[4];
    const float* W_op   = (const float*)d_in[5];
    const float* ff1    = (const float*)d_in[6];
    const float* ff1_b  = (const float*)d_in[7];
    const float* ff2    = (const float*)d_in[8];
    const float* ff2_b  = (const float*)d_in[9];
    const float* gamma  = (const float*)d_in[10];
    const float* beta   = (const float*)d_in[11];
    float* out = (float*)d_out;

    float *v, *lg, *h2, *T;
    __nv_bfloat16 *xhi, *xlo, *phi, *plo, *ohi, *olo, *h1hi, *h1lo;
    __nv_bfloat16 *wvhi, *wvlo, *wohi, *wolo, *f1hi, *f1lo, *f2hi, *f2lo;
    cudaGetSymbolAddress((void**)&v,   g_v);
    cudaGetSymbolAddress((void**)&lg,  g_lg);
    cudaGetSymbolAddress((void**)&h2,  g_h2);
    cudaGetSymbolAddress((void**)&T,   g_T);
    cudaGetSymbolAddress((void**)&xhi, g_xhi);  cudaGetSymbolAddress((void**)&xlo, g_xlo);
    cudaGetSymbolAddress((void**)&phi, g_phi);  cudaGetSymbolAddress((void**)&plo, g_plo);
    cudaGetSymbolAddress((void**)&ohi, g_ohi);  cudaGetSymbolAddress((void**)&olo, g_olo);
    cudaGetSymbolAddress((void**)&h1hi, g_h1hi); cudaGetSymbolAddress((void**)&h1lo, g_h1lo);
    cudaGetSymbolAddress((void**)&wvhi, g_wvhi); cudaGetSymbolAddress((void**)&wvlo, g_wvlo);
    cudaGetSymbolAddress((void**)&wohi, g_wohi); cudaGetSymbolAddress((void**)&wolo, g_wolo);
    cudaGetSymbolAddress((void**)&f1hi, g_f1hi); cudaGetSymbolAddress((void**)&f1lo, g_f1lo);
    cudaGetSymbolAddress((void**)&f2hi, g_f2hi); cudaGetSymbolAddress((void**)&f2lo, g_f2lo);

    cudaFuncSetAttribute(mma_gemm<0,0>, cudaFuncAttributeMaxDynamicSharedMemorySize, SMEM_GEMM);
    cudaFuncSetAttribute(mma_gemm<1,1>, cudaFuncAttributeMaxDynamicSharedMemorySize, SMEM_GEMM);
    cudaFuncSetAttribute(mma_gemm<2,1>, cudaFuncAttributeMaxDynamicSharedMemorySize, SMEM_GEMM);
    cudaFuncSetAttribute(mma_gemm<2,0>, cudaFuncAttributeMaxDynamicSharedMemorySize, SMEM_GEMM);

    const dim3 tgrid(2048 / TN, BS / TM);   // (16, 64)

    // Launch order: v-GEMM is the 4th launch (index 3) -> ncu capture target.
    conv_pair_kernel<<<(BS * DD / 4 + 255) / 256, 256>>>(x, xhi, xlo, BS * DD / 4);  // 0
    convT_kernel<<<dim3(HK / 32, DD / 32), 256>>>(W_val, wvhi, wvlo, DD, HK);        // 1
    att_logits_kernel<<<BS / 4, 256>>>(x, W_att, lg);                                 // 2

    // 3: v = x @ W_values (fp32 out for the scan)  <-- profiled launch
    mma_gemm<0,0><<<tgrid, 256, SMEM_GEMM>>>(xhi, xlo, xhi, xlo, DD,
        wvhi, wvlo, nullptr, v, nullptr, nullptr, HK, DD);

    coef_kernel<<<BB * HH, 256>>>(lg, temp);                                          // 4

    // pooled = coef * cumsum(v) -> bf16 hi/lo
    scan1_kernel<<<dim3(HK / 256, NSEG, BB), 256>>>(v, T);                            // 5
    scan2_kernel<<<dim3(HK / 256, NSEG, BB), 256>>>(v, T, lg, phi, plo);              // 6

    convT_kernel<<<dim3(VDIM / 32, HK / 32), 256>>>(W_op, wohi, wolo, HK, VDIM);     // 7
    convT_kernel<<<dim3(DD / 32, (VDIM + DD) / 32), 256>>>(ff1, f1hi, f1lo, VDIM + DD, DD); // 8
    convT_kernel<<<dim3(DD / 32, DD / 32), 256>>>(ff2, f2hi, f2lo, DD, DD);           // 9

    // op = pooled @ W_op + vector -> bf16 hi/lo
    mma_gemm<1,1><<<tgrid, 256, SMEM_GEMM>>>(phi, plo, phi, plo, HK,
        wohi, wolo, vector, nullptr, ohi, olo, VDIM, HK);                             // 10

    // h1 = relu([x, op] @ ff1 + b1) -> bf16 hi/lo   (split-A, K=4096)
    mma_gemm<2,1><<<tgrid, 256, SMEM_GEMM>>>(xhi, xlo, ohi, olo, DD,
        f1hi, f1lo, ff1_b, nullptr, h1hi, h1lo, DD, VDIM + DD);                       // 11

    // h2 = relu(h1 @ ff2 + b2) -> fp32
    mma_gemm<2,0><<<tgrid, 256, SMEM_GEMM>>>(h1hi, h1lo, h1hi, h1lo, DD,
        f2hi, f2lo, ff2_b, h2, nullptr, nullptr, DD, DD);                             // 12

    // out = LayerNorm(h2 + x)
    ln_kernel<<<BS, 256>>>(h2, x, gamma, beta, out);                                  // 13
}

// round 16
// speedup vs baseline: 1.0234x; 1.0148x over previous
#include <cuda_runtime.h>
#include <cuda_bf16.h>
#include <cstdint>
#include <cstddef>

#define BB    4
#define SS    2048
#define DD    2048
#define HH    16
#define HK    2048
#define VDIM  2048
#define BS    (BB*SS)
#define NSEG  16
#define SEGLEN (SS/NSEG)

// GEMM tiling: CTA 128x128, K-chunk 32, 8 warps (2m x 4n), warp 64x32
// SMEM: XOR-swizzled rows (64B, no pad), 3-stage cp.async pipeline, 2 CTAs/SM
#define TM 128
#define TN 128
#define TK 32
#define TILEB (128*64)           // 8192 B per tile (A/B, hi/lo)
#define STB   (4*TILEB)          // 32768 B per stage
#define NSTAGE 3
#define SMEM_GEMM (NSTAGE*STB)   // 98304 B -> 2 CTAs/SM

// ---------------- scratch (device globals; allocation forbidden) -----------
__device__ __align__(256) float g_v [(size_t)BS * HK];
__device__ __align__(256) float g_lg[(size_t)BS * HH];
__device__ __align__(256) float g_h2[(size_t)BS * DD];
__device__ __align__(256) float g_T [(size_t)BB * NSEG * HK];

__device__ __align__(256) __nv_bfloat16 g_xhi [(size_t)BS * DD];
__device__ __align__(256) __nv_bfloat16 g_xlo [(size_t)BS * DD];
__device__ __align__(256) __nv_bfloat16 g_phi [(size_t)BS * HK];
__device__ __align__(256) __nv_bfloat16 g_plo [(size_t)BS * HK];
__device__ __align__(256) __nv_bfloat16 g_ohi [(size_t)BS * VDIM];
__device__ __align__(256) __nv_bfloat16 g_olo [(size_t)BS * VDIM];
__device__ __align__(256) __nv_bfloat16 g_h1hi[(size_t)BS * DD];
__device__ __align__(256) __nv_bfloat16 g_h1lo[(size_t)BS * DD];

__device__ __align__(256) __nv_bfloat16 g_wvhi[(size_t)HK * DD];
__device__ __align__(256) __nv_bfloat16 g_wvlo[(size_t)HK * DD];
__device__ __align__(256) __nv_bfloat16 g_wohi[(size_t)VDIM * HK];
__device__ __align__(256) __nv_bfloat16 g_wolo[(size_t)VDIM * HK];
__device__ __align__(256) __nv_bfloat16 g_f1hi[(size_t)DD * (VDIM + DD)];
__device__ __align__(256) __nv_bfloat16 g_f1lo[(size_t)DD * (VDIM + DD)];
__device__ __align__(256) __nv_bfloat16 g_f2hi[(size_t)DD * DD];
__device__ __align__(256) __nv_bfloat16 g_f2lo[(size_t)DD * DD];

// ---------------- helpers ---------------------------------------------------
__device__ __forceinline__ uint32_t smem_u32(const void* p) {
    uint32_t a;
    asm("{ .reg .u64 t; cvta.to.shared.u64 t, %1; cvt.u32.u64 %0, t; }" : "=r"(a) : "l"(p));
    return a;
}
__device__ __forceinline__ void cp16(uint32_t s, const void* g) {
    asm volatile("cp.async.cg.shared.global [%0], [%1], 16;" :: "r"(s), "l"(g));
}
__device__ __forceinline__ void ldm4(uint32_t* r, uint32_t a) {
    asm volatile("ldmatrix.sync.aligned.m8n8.x4.shared.b16 {%0,%1,%2,%3}, [%4];"
        : "=r"(r[0]), "=r"(r[1]), "=r"(r[2]), "=r"(r[3]) : "r"(a));
}
__device__ __forceinline__ void mma16816(float* d, const uint32_t* a, const uint32_t* b) {
    asm volatile("mma.sync.aligned.m16n8k16.row.col.f32.bf16.bf16.f32 "
        "{%0,%1,%2,%3}, {%4,%5,%6,%7}, {%8,%9}, {%0,%1,%2,%3};"
        : "+f"(d[0]), "+f"(d[1]), "+f"(d[2]), "+f"(d[3])
        : "r"(a[0]), "r"(a[1]), "r"(a[2]), "r"(a[3]), "r"(b[0]), "r"(b[1]));
}
__device__ __forceinline__ void bf16_split(float v, __nv_bfloat16& h, __nv_bfloat16& l) {
    h = __float2bfloat16(v);
    l = __float2bfloat16(v - __bfloat162float(h));
}
__device__ __forceinline__ uint32_t swz(int row, int ch) {
    return (uint32_t)(row * 64 + ((ch ^ ((row >> 1) & 3)) << 4));
}

// ---------------------------------------------------------------------------
// split-bf16 GEMM via mma.sync (proven R12 shape).
// ---------------------------------------------------------------------------
template<int EPI, int OUTBF>
__global__ __launch_bounds__(256, 2) void mma_gemm(
    const __nv_bfloat16* __restrict__ A0h, const __nv_bfloat16* __restrict__ A0l,
    const __nv_bfloat16* __restrict__ A1h, const __nv_bfloat16* __restrict__ A1l,
    int ksplit,
    const __nv_bfloat16* __restrict__ Bh, const __nv_bfloat16* __restrict__ Bl,
    const float* __restrict__ bias,
    float* __restrict__ Cf, __nv_bfloat16* __restrict__ Chi, __nv_bfloat16* __restrict__ Clo,
    int N, int K)
{
    extern __shared__ char smem_raw[];
    const uint32_t sb = smem_u32(smem_raw);

    const int tid  = threadIdx.x;
    const int lane = tid & 31;
    const int warp = tid >> 5;
    const int wm   = warp >> 2;
    const int wn   = warp & 3;
    const int row0 = blockIdx.y * TM;
    const int col0 = blockIdx.x * TN;
    const int lda1 = K - ksplit;
    const int nch  = K / TK;

    float acc[4][4][4];
    #pragma unroll
    for (int a = 0; a < 4; a++)
        #pragma unroll
        for (int b = 0; b < 4; b++)
            #pragma unroll
            for (int c = 0; c < 4; c++) acc[a][b][c] = 0.f;

    auto load_stage = [&](int i) {
        const uint32_t base = sb + (i % NSTAGE) * STB;
        const int kt = i * TK;
        const __nv_bfloat16 *ah, *al; int lda, koff;
        if (kt < ksplit) { ah = A0h; al = A0l; lda = ksplit; koff = kt; }
        else             { ah = A1h; al = A1l; lda = lda1;   koff = kt - ksplit; }
        #pragma unroll
        for (int it = 0; it < 2; ++it) {
            const int f = tid + it * 256;
            const int row = f >> 2, ch = f & 3;
            const uint32_t so = base + swz(row, ch);
            const size_t ga = (size_t)(row0 + row) * lda + koff + ch * 8;
            cp16(so,          ah + ga);
            cp16(so + TILEB,  al + ga);
            const size_t gb = (size_t)(col0 + row) * K + kt + ch * 8;
            cp16(so + 2 * TILEB, Bh + gb);
            cp16(so + 3 * TILEB, Bl + gb);
        }
        asm volatile("cp.async.commit_group;" ::: "memory");
    };

    load_stage(0);
    load_stage(1);
    for (int i = 0; i < nch; ++i) {
        if (i + 2 < nch) {
            load_stage(i + 2);
            asm volatile("cp.async.wait_group 2;" ::: "memory");
        } else if (i + 1 < nch) {
            asm volatile("cp.async.wait_group 1;" ::: "memory");
        } else {
            asm volatile("cp.async.wait_group 0;" ::: "memory");
        }
        __syncthreads();

        const uint32_t ab  = sb + (i % NSTAGE) * STB;
        const uint32_t alb = ab + TILEB;
        const uint32_t bb  = ab + 2 * TILEB;
        const uint32_t blb = ab + 3 * TILEB;
        #pragma unroll
        for (int ks = 0; ks < 2; ++ks) {
            uint32_t af[4][4], alf[4][4], bfr[2][4];
            const int axor = ((lane & 15) >> 1) & 3;
            const uint32_t aofs = (uint32_t)((lane & 15) * 64
                                  + (((ks * 2 + (lane >> 4)) ^ axor) << 4));
            #pragma unroll
            for (int mt = 0; mt < 4; ++mt) {
                const uint32_t r = (uint32_t)((wm * 64 + mt * 16) * 64) + aofs;
                ldm4(af[mt],  ab  + r);
                ldm4(alf[mt], alb + r);
            }
            const int bxor = ((lane & 7) >> 1) & 3;
            const uint32_t bofs = (uint32_t)(((((lane >> 4) << 3) + (lane & 7)) * 64)
                                  + (((ks * 2 + ((lane >> 3) & 1)) ^ bxor) << 4));
            #pragma unroll
            for (int np = 0; np < 2; ++np)
                ldm4(bfr[np], bb + (uint32_t)((wn * 32 + np * 16) * 64) + bofs);
            #pragma unroll
            for (int mt = 0; mt < 4; ++mt)
                #pragma unroll
                for (int nt = 0; nt < 4; ++nt)
                    mma16816(acc[mt][nt], af[mt], &bfr[nt >> 1][(nt & 1) * 2]);
            #pragma unroll
            for (int mt = 0; mt < 4; ++mt)
                #pragma unroll
                for (int nt = 0; nt < 4; ++nt)
                    mma16816(acc[mt][nt], alf[mt], &bfr[nt >> 1][(nt & 1) * 2]);
            #pragma unroll
            for (int np = 0; np < 2; ++np)
                ldm4(bfr[np], blb + (uint32_t)((wn * 32 + np * 16) * 64) + bofs);
            #pragma unroll
            for (int mt = 0; mt < 4; ++mt)
                #pragma unroll
                for (int nt = 0; nt < 4; ++nt)
                    mma16816(acc[mt][nt], af[mt], &bfr[nt >> 1][(nt & 1) * 2]);
        }
        __syncthreads();
    }

    const int mrow = lane >> 2;
    const int ncol = (lane & 3) * 2;
    #pragma unroll
    for (int mt = 0; mt < 4; ++mt)
        #pragma unroll
        for (int nt = 0; nt < 4; ++nt) {
            const int gc = col0 + wn * 32 + nt * 8 + ncol;
            #pragma unroll
            for (int hrow = 0; hrow < 2; ++hrow) {
                const int r = row0 + wm * 64 + mt * 16 + mrow + hrow * 8;
                float v0 = acc[mt][nt][hrow * 2];
                float v1 = acc[mt][nt][hrow * 2 + 1];
                if (EPI == 1) {
                    const float* bv = bias + (size_t)(r / SS) * N;
                    v0 += bv[gc]; v1 += bv[gc + 1];
                } else if (EPI == 2) {
                    v0 = fmaxf(v0 + bias[gc], 0.f);
                    v1 = fmaxf(v1 + bias[gc + 1], 0.f);
                }
                if (OUTBF) {
                    __nv_bfloat162 hp, lp;
                    bf16_split(v0, hp.x, lp.x);
                    bf16_split(v1, hp.y, lp.y);
                    *reinterpret_cast<__nv_bfloat162*>(Chi + (size_t)r * N + gc) = hp;
                    *reinterpret_cast<__nv_bfloat162*>(Clo + (size_t)r * N + gc) = lp;
                } else {
                    *reinterpret_cast<float2*>(Cf + (size_t)r * N + gc) = make_float2(v0, v1);
                }
            }
        }
}

// ---------------- fp32 -> bf16 hi/lo split ---------------------------------
__global__ __launch_bounds__(256) void conv_pair_kernel(
    const float* __restrict__ in, __nv_bfloat16* __restrict__ hi,
    __nv_bfloat16* __restrict__ lo, int n4)
{
    const int i = blockIdx.x * 256 + threadIdx.x;
    if (i >= n4) return;
    const float4 v = reinterpret_cast<const float4*>(in)[i];
    __nv_bfloat162 h01, h23, l01, l23;
    bf16_split(v.x, h01.x, l01.x);
    bf16_split(v.y, h01.y, l01.y);
    bf16_split(v.z, h23.x, l23.x);
    bf16_split(v.w, h23.y, l23.y);
    reinterpret_cast<__nv_bfloat162*>(hi)[2 * (size_t)i]     = h01;
    reinterpret_cast<__nv_bfloat162*>(hi)[2 * (size_t)i + 1] = h23;
    reinterpret_cast<__nv_bfloat162*>(lo)[2 * (size_t)i]     = l01;
    reinterpret_cast<__nv_bfloat162*>(lo)[2 * (size_t)i + 1] = l23;
}

// ---------------- W [K,N] fp32 -> Th/Tl [N,K] bf16 (transpose+split) -------
__global__ __launch_bounds__(256) void convT_kernel(
    const float* __restrict__ W, __nv_bfloat16* __restrict__ Th,
    __nv_bfloat16* __restrict__ Tl, int K, int N)
{
    __shared__ float t[32][33];
    const int k0 = blockIdx.y * 32, n0 = blockIdx.x * 32;
    const int tx = threadIdx.x & 31, ty = threadIdx.x >> 5;
    #pragma unroll
    for (int i = 0; i < 32; i += 8)
        t[ty + i][tx] = W[(size_t)(k0 + ty + i) * N + n0 + tx];
    __syncthreads();
    #pragma unroll
    for (int i = 0; i < 32; i += 8) {
        const float v = t[tx][ty + i];
        __nv_bfloat16 h, l;
        bf16_split(v, h, l);
        const size_t o = (size_t)(n0 + ty + i) * K + k0 + tx;
        Th[o] = h;
        Tl[o] = l;
    }
}

// ---------------- attention-gate logits ------------------------------------
__global__ __launch_bounds__(256) void att_logits_kernel(
    const float* __restrict__ x, const float* __restrict__ Watt,
    float* __restrict__ logits)
{
    __shared__ float xs[4][DD];
    __shared__ float red[4][256];
    const int r0 = blockIdx.x * 4;
    #pragma unroll
    for (int rr = 0; rr < 4; rr++)
        for (int i = threadIdx.x; i < DD; i += 256)
            xs[rr][i] = x[(size_t)(r0 + rr) * DD + i];
    __syncthreads();
    const int h = threadIdx.x & 15, ks = threadIdx.x >> 4;
    float acc[4] = {0.f, 0.f, 0.f, 0.f};
    for (int i = 0; i < DD; i += 16) {
        const float wv = Watt[(i + ks) * HH + h];
        #pragma unroll
        for (int rr = 0; rr < 4; rr++) acc[rr] += xs[rr][i + ks] * wv;
    }
    #pragma unroll
    for (int rr = 0; rr < 4; rr++) red[rr][threadIdx.x] = acc[rr];
    __syncthreads();
    if (threadIdx.x < 64) {
        const int rr = threadIdx.x >> 4, hh = threadIdx.x & 15;
        float s = 0.f;
        #pragma unroll
        for (int g = 0; g < 16; g++) s += red[rr][g * 16 + hh];
        logits[(size_t)(r0 + rr) * HH + hh] = s;
    }
}

// ---------------- coef (in-place on logits) --------------------------------
__global__ __launch_bounds__(256) void coef_kernel(
    float* __restrict__ lg, const float* __restrict__ temp)
{
    __shared__ float sb[8];
    const int b = blockIdx.x >> 4, h = blockIdx.x & 15;
    float* base = lg + (size_t)b * SS * HH + h;
    float m = -1e30f;
    for (int s = threadIdx.x; s < SS; s += 256)
        m = fmaxf(m, base[(size_t)s * HH]);
    #pragma unroll
    for (int o = 16; o; o >>= 1) m = fmaxf(m, __shfl_xor_sync(0xffffffffu, m, o));
    if ((threadIdx.x & 31) == 0) sb[threadIdx.x >> 5] = m;
    __syncthreads();
    float mm = sb[0];
    #pragma unroll
    for (int i = 1; i < 8; i++) mm = fmaxf(mm, sb[i]);
    const float T = temp[h];
    for (int s = threadIdx.x; s < SS; s += 256) {
        const float w = expf((base[(size_t)s * HH] - mm) * T);
        base[(size_t)s * HH] = w / (w * (float)(s + 1) + 1e-30f);
    }
}

// ---------------- 2-phase segmented causal scan ----------------------------
__global__ __launch_bounds__(256) void scan1_kernel(
    const float* __restrict__ v, float* __restrict__ T)
{
    const int c = blockIdx.x * 256 + threadIdx.x;
    const int seg = blockIdx.y, b = blockIdx.z;
    const float* p = v + ((size_t)b * SS + seg * SEGLEN) * HK + c;
    float a = 0.f;
    #pragma unroll 4
    for (int s = 0; s < SEGLEN; s++) a += p[(size_t)s * HK];
    T[((size_t)b * NSEG + seg) * HK + c] = a;
}

__global__ __launch_bounds__(256) void scan2_kernel(
    const float* __restrict__ v, const float* __restrict__ T,
    const float* __restrict__ coef,
    __nv_bfloat16* __restrict__ ph, __nv_bfloat16* __restrict__ pl)
{
    const int c = blockIdx.x * 256 + threadIdx.x;
    const int seg = blockIdx.y, b = blockIdx.z;
    float a = 0.f;
    for (int t = 0; t < seg; t++) a += T[((size_t)b * NSEG + t) * HK + c];
    const size_t rbase = ((size_t)b * SS + seg * SEGLEN) * HK + c;
    const float* p  = v + rbase;
    const float* cf = coef + (size_t)b * SS * HH + (size_t)seg * SEGLEN * HH + (c >> 7);
    #pragma unroll 4
    for (int s = 0; s < SEGLEN; s++) {
        a += p[(size_t)s * HK];
        const float val = cf[(size_t)s * HH] * a;
        __nv_bfloat16 h, l;
        bf16_split(val, h, l);
        ph[rbase + (size_t)s * HK] = h;
        pl[rbase + (size_t)s * HK] = l;
    }
}

// ---------------- LayerNorm ------------------------------------------------
__device__ __forceinline__ float block_sum_256(float v) {
    __shared__ float sb[8];
    #pragma unroll
    for (int o = 16; o; o >>= 1) v += __shfl_xor_sync(0xffffffffu, v, o);
    if ((threadIdx.x & 31) == 0) sb[threadIdx.x >> 5] = v;
    __syncthreads();
    float s = 0.f;
    #pragma unroll
    for (int i = 0; i < 8; i++) s += sb[i];
    __syncthreads();
    return s;
}

__global__ __launch_bounds__(256) void ln_kernel(
    const float* __restrict__ h2, const float* __restrict__ x,
    const float* __restrict__ gamma, const float* __restrict__ beta,
    float* __restrict__ out)
{
    const size_t base = (size_t)blockIdx.x * DD;
    float v[8];
    float s = 0.f;
    #pragma unroll
    for (int j = 0; j < 8; j++) {
        const int c = threadIdx.x + j * 256;
        v[j] = h2[base + c] + x[base + c];
        s += v[j];
    }
    s = block_sum_256(s);
    const float mean = s * (1.f / DD);
    float q = 0.f;
    #pragma unroll
    for (int j = 0; j < 8; j++) { v[j] -= mean; q += v[j] * v[j]; }
    q = block_sum_256(q);
    const float inv = rsqrtf(q * (1.f / DD) + 1e-6f);
    #pragma unroll
    for (int j = 0; j < 8; j++) {
        const int c = threadIdx.x + j * 256;
        out[base + c] = v[j] * inv * gamma[c] + beta[c];
    }
}

// ---------------- kernel_launch --------------------------------------------
extern "C" void kernel_launch(void* const* d_in, const int* in_sizes, int n_in,
                              void* d_out, int out_size)
{
    (void)in_sizes; (void)n_in; (void)out_size;
    const float* x      = (const float*)d_in[0];
    const float* vector = (const float*)d_in[1];
    const float* W_att  = (const float*)d_in[2];
    const float* temp   = (const float*)d_in[3];
    const float* W_val  = (const float*)d_in[4];
    const float* W_op   = (const float*)d_in[5];
    const float* ff1    = (const float*)d_in[6];
    const float* ff1_b  = (const float*)d_in[7];
    const float* ff2    = (const float*)d_in[8];
    const float* ff2_b  = (const float*)d_in[9];
    const float* gamma  = (const float*)d_in[10];
    const float* beta   = (const float*)d_in[11];
    float* out = (float*)d_out;

    float *v, *lg, *h2, *T;
    __nv_bfloat16 *xhi, *xlo, *phi, *plo, *ohi, *olo, *h1hi, *h1lo;
    __nv_bfloat16 *wvhi, *wvlo, *wohi, *wolo, *f1hi, *f1lo, *f2hi, *f2lo;
    cudaGetSymbolAddress((void**)&v,   g_v);
    cudaGetSymbolAddress((void**)&lg,  g_lg);
    cudaGetSymbolAddress((void**)&h2,  g_h2);
    cudaGetSymbolAddress((void**)&T,   g_T);
    cudaGetSymbolAddress((void**)&xhi, g_xhi);  cudaGetSymbolAddress((void**)&xlo, g_xlo);
    cudaGetSymbolAddress((void**)&phi, g_phi);  cudaGetSymbolAddress((void**)&plo, g_plo);
    cudaGetSymbolAddress((void**)&ohi, g_ohi);  cudaGetSymbolAddress((void**)&olo, g_olo);
    cudaGetSymbolAddress((void**)&h1hi, g_h1hi); cudaGetSymbolAddress((void**)&h1lo, g_h1lo);
    cudaGetSymbolAddress((void**)&wvhi, g_wvhi); cudaGetSymbolAddress((void**)&wvlo, g_wvlo);
    cudaGetSymbolAddress((void**)&wohi, g_wohi); cudaGetSymbolAddress((void**)&wolo, g_wolo);
    cudaGetSymbolAddress((void**)&f1hi, g_f1hi); cudaGetSymbolAddress((void**)&f1lo, g_f1lo);
    cudaGetSymbolAddress((void**)&f2hi, g_f2hi); cudaGetSymbolAddress((void**)&f2lo, g_f2lo);

    cudaFuncSetAttribute(mma_gemm<0,0>, cudaFuncAttributeMaxDynamicSharedMemorySize, SMEM_GEMM);
    cudaFuncSetAttribute(mma_gemm<1,1>, cudaFuncAttributeMaxDynamicSharedMemorySize, SMEM_GEMM);
    cudaFuncSetAttribute(mma_gemm<2,1>, cudaFuncAttributeMaxDynamicSharedMemorySize, SMEM_GEMM);
    cudaFuncSetAttribute(mma_gemm<2,0>, cudaFuncAttributeMaxDynamicSharedMemorySize, SMEM_GEMM);

    // One-time stream/event creation (first call is the non-captured
    // correctness run; creation must not happen during capture).
    static cudaStream_t s1 = nullptr, s2 = nullptr;
    static cudaEvent_t eFork = nullptr, eWv = nullptr, eW = nullptr, eCoef = nullptr;
    if (!s1) {
        cudaStreamCreateWithFlags(&s1, cudaStreamNonBlocking);
        cudaStreamCreateWithFlags(&s2, cudaStreamNonBlocking);
        cudaEventCreateWithFlags(&eFork, cudaEventDisableTiming);
        cudaEventCreateWithFlags(&eWv,   cudaEventDisableTiming);
        cudaEventCreateWithFlags(&eW,    cudaEventDisableTiming);
        cudaEventCreateWithFlags(&eCoef, cudaEventDisableTiming);
    }

    const dim3 tgrid(2048 / TN, BS / TM);   // (16, 64)

    // -------- fork: side branches join the capture via eFork ---------------
    cudaEventRecord(eFork, 0);
    cudaStreamWaitEvent(s1, eFork, 0);
    cudaStreamWaitEvent(s2, eFork, 0);

    // s1: weight conversions. wv first (gates v-GEMM); wo/f1/f2 overlap the
    // v-GEMM itself (and fill its last-wave tail).
    convT_kernel<<<dim3(HK / 32, DD / 32), 256, 0, s1>>>(W_val, wvhi, wvlo, DD, HK);
    cudaEventRecord(eWv, s1);
    convT_kernel<<<dim3(VDIM / 32, HK / 32), 256, 0, s1>>>(W_op, wohi, wolo, HK, VDIM);
    convT_kernel<<<dim3(DD / 32, (VDIM + DD) / 32), 256, 0, s1>>>(ff1, f1hi, f1lo, VDIM + DD, DD);
    convT_kernel<<<dim3(DD / 32, DD / 32), 256, 0, s1>>>(ff2, f2hi, f2lo, DD, DD);
    cudaEventRecord(eW, s1);

    // s2: attention gate (independent of everything until scan2)
    att_logits_kernel<<<BS / 4, 256, 0, s2>>>(x, W_att, lg);
    coef_kernel<<<BB * HH, 256, 0, s2>>>(lg, temp);
    cudaEventRecord(eCoef, s2);

    // s0 (legacy): main dependency chain
    conv_pair_kernel<<<(BS * DD / 4 + 255) / 256, 256>>>(x, xhi, xlo, BS * DD / 4);
    cudaStreamWaitEvent(0, eWv, 0);

    // v = x @ W_values (fp32 out for the scan)
    mma_gemm<0,0><<<tgrid, 256, SMEM_GEMM>>>(xhi, xlo, xhi, xlo, DD,
        wvhi, wvlo, nullptr, v, nullptr, nullptr, HK, DD);

    // pooled = coef * cumsum(v) -> bf16 hi/lo
    scan1_kernel<<<dim3(HK / 256, NSEG, BB), 256>>>(v, T);
    cudaStreamWaitEvent(0, eCoef, 0);
    scan2_kernel<<<dim3(HK / 256, NSEG, BB), 256>>>(v, T, lg, phi, plo);

    cudaStreamWaitEvent(0, eW, 0);

    // op = pooled @ W_op + vector -> bf16 hi/lo
    mma_gemm<1,1><<<tgrid, 256, SMEM_GEMM>>>(phi, plo, phi, plo, HK,
        wohi, wolo, vector, nullptr, ohi, olo, VDIM, HK);

    // h1 = relu([x, op] @ ff1 + b1) -> bf16 hi/lo   (split-A, K=4096)
    mma_gemm<2,1><<<tgrid, 256, SMEM_GEMM>>>(xhi, xlo, ohi, olo, DD,
        f1hi, f1lo, ff1_b, nullptr, h1hi, h1lo, DD, VDIM + DD);

    // h2 = relu(h1 @ ff2 + b2) -> fp32
    mma_gemm<2,0><<<tgrid, 256, SMEM_GEMM>>>(h1hi, h1lo, h1hi, h1lo, DD,
        f2hi, f2lo, ff2_b, h2, nullptr, nullptr, DD, DD);

    // out = LayerNorm(h2 + x)
    ln_kernel<<<BS, 256>>>(h2, x, gamma, beta, out);
}